// round 15
// baseline (speedup 1.0000x reference)
#include <cuda_runtime.h>
#include <cuda_fp16.h>
#include <math.h>
#include <stdint.h>

#define NTOK 64
#define CDIM 256
#define NHEADS 8
#define HD   32
#define NWIN 64
#define NBATCH 2048
#define THREADS 256

// strides in uint32 (half2) units
#define S2Q 68            // qs: 4 mod 32 -> conflict-free qr-row access
#define S2K 72            // kbuf: 8 mod 32 -> conflict-free ql-row access
#define S2V 136           // vbuf: 8 mod 32
#define S2W 136           // weight stages: 8 mod 32

// smem layout (uint32 units)
#define OFF_Q  0                        // 64 x 68
#define OFF_K  (64 * S2Q)               // 64 x 72 (K data) / 32 x 136 stage overlay
#define OFF_V  (OFF_K + 64 * S2K)       // 32 x 136 (V data / stage overlay)
#define OFF_WA (OFF_V + 32 * S2V)       // 32 x 136
#define OFF_WB (OFF_WA + 32 * S2W)      // 32 x 136
#define SMEM_U32 (OFF_WB + 32 * S2W)
#define SMEM_BYTES (SMEM_U32 * 4)       // 88064 B -> 2 CTAs/SM

__device__ float d_tbl2[225 * NHEADS];
__device__ float d_Tcomb[NWIN * NHEADS * NTOK * NTOK];   // 16*sigmoid(bias)+mask, 8MB
__device__ uint32_t d_wh[4 * 2 * 2 * 32 * 128];          // fp16 k-pair packed weights

// ---------------- helpers ----------------
__device__ __forceinline__ uint32_t pkh2(float a, float b) {
    __half2 h = __floats2half2_rn(a, b);
    return *reinterpret_cast<uint32_t*>(&h);
}
__device__ __forceinline__ float2 uph2(uint32_t u) {
    __half2 h = *reinterpret_cast<__half2*>(&u);
    return __half22float2(h);
}

// ---------------- fused prologue: weight pack (blocks 0..511) + CPB MLP (512..736) ----------------
__global__ void prologue_kernel(const float* __restrict__ qw, const float* __restrict__ kw,
                                const float* __restrict__ vw, const float* __restrict__ pw,
                                const float* __restrict__ rpb, const float* __restrict__ w1,
                                const float* __restrict__ b1, const float* __restrict__ w2) {
    if (blockIdx.x < 512) {
        int idx = blockIdx.x * 256 + threadIdx.x;    // < 131072
        int w  = idx >> 14;
        int s  = (idx >> 13) & 1;
        int hf = (idx >> 12) & 1;
        int kk = (idx >> 7) & 31;
        int n  = idx & 127;
        const float* src = (w == 0) ? qw : (w == 1) ? kw : (w == 2) ? vw : pw;
        int c = hf * 64 + 2 * kk;
        float v0 = src[s * 16384 + c * 128 + n];
        float v1 = src[s * 16384 + (c + 1) * 128 + n];
        d_wh[idx] = pkh2(v0, v1);
    } else {
        __shared__ float acc[NHEADS];
        int p = blockIdx.x - 512;                    // 0..224
        int j = threadIdx.x;                         // 0..255; hidden dim is 128
        if (j < NHEADS) acc[j] = 0.f;
        __syncthreads();
        float t0 = rpb[p * 2 + 0];
        float t1 = rpb[p * 2 + 1];
        float hid = 0.f;
        if (j < 128) hid = fmaxf(t0 * w1[j] + t1 * w1[128 + j] + b1[j], 0.f);
#pragma unroll
        for (int h = 0; h < NHEADS; ++h) {
            float pv = (j < 128) ? hid * w2[j * 8 + h] : 0.f;
#pragma unroll
            for (int o = 16; o; o >>= 1) pv += __shfl_xor_sync(0xffffffffu, pv, o);
            if ((j & 31) == 0) atomicAdd(&acc[h], pv);
        }
        __syncthreads();
        if (j < NHEADS) d_tbl2[p * 8 + j] = acc[j];
    }
}

// ---------------- prologue 2: combined bias+mask table ----------------
__global__ void bias_combine_kernel(const int* __restrict__ rpi,
                                    const float* __restrict__ mask) {
    int idx = blockIdx.x * blockDim.x + threadIdx.x;
    if (idx >= NWIN * NHEADS * NTOK * NTOK) return;
    int ij = idx & 4095;
    int h  = (idx >> 12) & 7;
    int w  = idx >> 15;
    float bv = d_tbl2[rpi[ij] * 8 + h];
    d_Tcomb[idx] = 16.f / (1.f + expf(-bv)) + mask[w * 4096 + ij];
}

// ---------------- fp16 mma m16n8k16 ----------------
__device__ __forceinline__ void mma_f16(float& d0, float& d1, float& d2, float& d3,
                                        uint32_t a0, uint32_t a1, uint32_t a2, uint32_t a3,
                                        uint32_t b0, uint32_t b1) {
    asm volatile(
        "mma.sync.aligned.m16n8k16.row.col.f32.f16.f16.f32 "
        "{%0,%1,%2,%3},{%4,%5,%6,%7},{%8,%9},{%0,%1,%2,%3};"
        : "+f"(d0), "+f"(d1), "+f"(d2), "+f"(d3)
        : "r"(a0), "r"(a1), "r"(a2), "r"(a3), "r"(b0), "r"(b1));
}

// weight source: w 0..3 = q,k,v,p; half hf -> [32 kk][128 n] uint32 block
#define WSRC(w, hf) (d_wh + (((w) * 2 + s) * 2 + (hf)) * 4096)

// stage one [32 kk][128 n] uint32 weight half via 4 cp.async per thread
#define ISSUE(SRC, DSTU) do {                                                \
    const uint32_t* _s0 = (SRC) + ldrow * 128 + ldcol;                       \
    uint32_t _d0 = (DSTU) + (uint32_t)((ldrow * S2W + ldcol) * 4);           \
    _Pragma("unroll")                                                        \
    for (int k_ = 0; k_ < 4; ++k_)                                           \
        asm volatile("cp.async.cg.shared.global [%0], [%1], 16;\n"           \
            :: "r"(_d0 + (uint32_t)(k_ * 8 * S2W * 4)),                      \
               "l"(_s0 + k_ * 8 * 128) : "memory");                          \
    asm volatile("cp.async.commit_group;\n" ::: "memory");                   \
} while (0)

#define WAITSYNC() do {                                                      \
    asm volatile("cp.async.wait_group 0;\n" ::: "memory");                   \
    __syncthreads();                                                         \
} while (0)

// 32x32 warp-tile fp16 mma over one staged weight half, A from af[AH]
#define MMA_LOOP(BUFU, ACC, AH) do {                                         \
    const uint32_t* _bu = (BUFU);                                            \
    _Pragma("unroll")                                                        \
    for (int kt = 0; kt < 4; ++kt) {                                         \
        const uint32_t* bp = _bu + (kt * 8 + ql) * S2W + n0 + qr;            \
        _Pragma("unroll")                                                    \
        for (int nt = 0; nt < 4; ++nt) {                                     \
            uint32_t b0_ = bp[nt * 8], b1_ = bp[4 * S2W + nt * 8];           \
            mma_f16(ACC[0][nt][0], ACC[0][nt][1], ACC[0][nt][2], ACC[0][nt][3], \
                    af[AH][0][kt][0], af[AH][0][kt][1], af[AH][0][kt][2], af[AH][0][kt][3], \
                    b0_, b1_);                                               \
            mma_f16(ACC[1][nt][0], ACC[1][nt][1], ACC[1][nt][2], ACC[1][nt][3], \
                    af[AH][1][kt][0], af[AH][1][kt][1], af[AH][1][kt][2], af[AH][1][kt][3], \
                    b0_, b1_);                                               \
        }                                                                    \
    }                                                                        \
} while (0)

// load A fragments for half HF into af[HF] (2 row tiles x 4 k16 tiles)
#define LOAD_AF_H(HF) do {                                                   \
    _Pragma("unroll")                                                        \
    for (int mt = 0; mt < 2; ++mt)                                           \
    _Pragma("unroll")                                                        \
    for (int kt = 0; kt < 4; ++kt) {                                         \
        const uint32_t* ap = qs2 + (r0 + mt * 16 + qr) * S2Q + (HF) * 32 + kt * 8 + ql; \
        af[HF][mt][kt][0] = ap[0];                                           \
        af[HF][mt][kt][1] = ap[8 * S2Q];                                     \
        af[HF][mt][kt][2] = ap[4];                                           \
        af[HF][mt][kt][3] = ap[8 * S2Q + 4];                                 \
    }                                                                        \
} while (0)

#define ZERO_ACC(A) do {                                                     \
    _Pragma("unroll")                                                        \
    for (int mt = 0; mt < 2; ++mt)                                           \
    _Pragma("unroll")                                                        \
    for (int nt = 0; nt < 4; ++nt)                                           \
        { A[mt][nt][0] = 0.f; A[mt][nt][1] = 0.f; A[mt][nt][2] = 0.f; A[mt][nt][3] = 0.f; } \
} while (0)

// ---------------- main fused kernel: one CTA per (window, branch) ----------------
__global__ void __launch_bounds__(THREADS, 2)
swin_branch_kernel(const float* __restrict__ x,
                   const float* __restrict__ qb, const float* __restrict__ kb,
                   const float* __restrict__ vb, const float* __restrict__ pb,
                   const float* __restrict__ ls, float* __restrict__ out)
{
    extern __shared__ uint32_t smU[];
    uint32_t* qs2   = smU + OFF_Q;    // x / q / O as fp16 pairs (64 x 68)
    uint32_t* kbufU = smU + OFF_K;    // K d-pair transposed [d/2=64][key 64] (stride 72)
    uint32_t* vbufU = smU + OFF_V;    // V token-pair [tok/2=32][d 128] (stride 136)
    uint32_t* kstgU = smU + OFF_K;    // K-weight stage overlay (stride 136, 32 rows)
    uint32_t* vstgU = smU + OFF_V;    // K-weight stage overlay half 1
    uint32_t* wstA  = smU + OFF_WA;
    uint32_t* wstB  = smU + OFF_WB;

    const int bid  = blockIdx.x;
    const int win  = bid >> 1;
    const int s    = bid & 1;               // branch (heads s*4..s*4+3)
    const int tid  = threadIdx.x;
    const int warp = tid >> 5;
    const int lane = tid & 31;
    const int r0   = (warp & 1) * 32;       // 32x32 warp tiles: 2 row x 4 col grid
    const int n0   = (warp >> 1) * 32;
    const int qr   = lane >> 2;
    const int ql   = lane & 3;
    const int ldrow = tid >> 5;             // staging row base 0..7
    const int ldcol = (tid & 31) * 4;       // staging col (uint32) 0..124

    const uint32_t wA_u = (uint32_t)__cvta_generic_to_shared(wstA);
    const uint32_t wB_u = (uint32_t)__cvta_generic_to_shared(wstB);
    const uint32_t kstg_u = (uint32_t)__cvta_generic_to_shared(kstgU);
    const uint32_t vstg_u = (uint32_t)__cvta_generic_to_shared(vstgU);

    uint32_t af[2][2][4][4];                // A frags, both halves, held across K/V/Q

    // batch-prefetch K (both halves) and V (both halves) weight stages
    ISSUE(WSRC(1, 0), kstg_u);
    ISSUE(WSRC(1, 1), vstg_u);
    ISSUE(WSRC(2, 0), wA_u);
    ISSUE(WSRC(2, 1), wB_u);

    // load x branch slice [64][128] -> fp16 pairs in qs
    const float4* xg4 = (const float4*)(x + (size_t)win * (NTOK * CDIM));
    for (int t = tid; t < 64 * 32; t += THREADS) {
        int i = t >> 5, j = t & 31;
        float4 v = xg4[i * 64 + s * 32 + j];
        uint2 st; st.x = pkh2(v.x, v.y); st.y = pkh2(v.z, v.w);
        *(uint2*)&qs2[i * S2Q + j * 2] = st;
    }
    WAITSYNC();                              // B1: x visible + all 4 stages landed

    LOAD_AF_H(0);
    LOAD_AF_H(1);

    // =========== Phase 1: K, V, Q residual linears ===========
    float accK[2][4][4];
    ZERO_ACC(accK);
    MMA_LOOP(kstgU, accK, 0);
    MMA_LOOP(vstgU, accK, 1);
    __syncthreads();                         // B2: stage overlay reads done

    {
        // V GEMM (weights already resident in wstA/B)
        float accV[2][4][4];
        ZERO_ACC(accV);
        MMA_LOOP(wstA, accV, 0);
        MMA_LOOP(wstB, accV, 1);

        // k epilogue: -> kbuf d-pair transposed [c/2][key] (overwrites kstg overlay)
#pragma unroll
        for (int mt = 0; mt < 2; ++mt) {
            const int rr = r0 + mt * 16 + qr;
#pragma unroll
            for (int nt = 0; nt < 4; ++nt) {
                const int c = n0 + nt * 8 + 2 * ql;
                float2 x0 = uph2(qs2[rr * S2Q + (c >> 1)]);
                float2 x1 = uph2(qs2[(rr + 8) * S2Q + (c >> 1)]);
                float2 kb2 = *(const float2*)&kb[s * 128 + c];
                kbufU[(c >> 1) * S2K + rr] =
                    pkh2(x0.x + accK[mt][nt][0] + kb2.x, x0.y + accK[mt][nt][1] + kb2.y);
                kbufU[(c >> 1) * S2K + rr + 8] =
                    pkh2(x1.x + accK[mt][nt][2] + kb2.x, x1.y + accK[mt][nt][3] + kb2.y);
            }
        }

        // v epilogue: token-pair pack via lane-xor-4 exchange -> vbuf (overwrites vstg)
#pragma unroll
        for (int mt = 0; mt < 2; ++mt) {
            const int rr = r0 + mt * 16 + qr;
            const int m0 = rr >> 1;
            const uint32_t psel = (qr & 1) ? 0x3276u : 0x5410u;
            const int cofs = (qr & 1);
#pragma unroll
            for (int nt = 0; nt < 4; ++nt) {
                const int c = n0 + nt * 8 + 2 * ql;
                float2 x0 = uph2(qs2[rr * S2Q + (c >> 1)]);
                float2 x1 = uph2(qs2[(rr + 8) * S2Q + (c >> 1)]);
                float2 vb2 = *(const float2*)&vb[s * 128 + c];
                uint32_t mine0 = pkh2(x0.x + accV[mt][nt][0] + vb2.x, x0.y + accV[mt][nt][1] + vb2.y);
                uint32_t mine1 = pkh2(x1.x + accV[mt][nt][2] + vb2.x, x1.y + accV[mt][nt][3] + vb2.y);
                uint32_t oth0 = __shfl_xor_sync(0xffffffffu, mine0, 4);
                uint32_t oth1 = __shfl_xor_sync(0xffffffffu, mine1, 4);
                vbufU[m0 * S2V + c + cofs]       = __byte_perm(mine0, oth0, psel);
                vbufU[(m0 + 4) * S2V + c + cofs] = __byte_perm(mine1, oth1, psel);
            }
        }
    }
    __syncthreads();                         // B3: wstA/B reads done
    ISSUE(WSRC(0, 0), wA_u);                 // Q weights
    ISSUE(WSRC(0, 1), wB_u);
    WAITSYNC();                              // B4

    {
        // Q GEMM + epilogue (own-position RMW; no barrier needed in between)
        float accQ[2][4][4];
        ZERO_ACC(accQ);
        MMA_LOOP(wstA, accQ, 0);
        MMA_LOOP(wstB, accQ, 1);
#pragma unroll
        for (int mt = 0; mt < 2; ++mt) {
            const int rr = r0 + mt * 16 + qr;
#pragma unroll
            for (int nt = 0; nt < 4; ++nt) {
                const int c = n0 + nt * 8 + 2 * ql;
                float2 x0 = uph2(qs2[rr * S2Q + (c >> 1)]);
                float2 x1 = uph2(qs2[(rr + 8) * S2Q + (c >> 1)]);
                float2 qb2 = *(const float2*)&qb[s * 128 + c];
                qs2[rr * S2Q + (c >> 1)] =
                    pkh2(x0.x + accQ[mt][nt][0] + qb2.x, x0.y + accQ[mt][nt][1] + qb2.y);
                qs2[(rr + 8) * S2Q + (c >> 1)] =
                    pkh2(x1.x + accQ[mt][nt][2] + qb2.x, x1.y + accQ[mt][nt][3] + qb2.y);
            }
        }
    }
    __syncthreads();                         // B5: MMA-Q reads done + q published
    ISSUE(WSRC(3, 0), wA_u);                 // P weights (consumed in phase 4)
    ISSUE(WSRC(3, 1), wB_u);

    // =========== Phase 2: l2-normalize q (qs) and k (kbuf); fold logit scale ===========
#pragma unroll
    for (int t4 = 0; t4 < 2; ++t4) {
        int t = tid + t4 * THREADS;          // 512 tasks
        int bufsel = t >> 8;
        int h = (t >> 6) & 3;
        int i = t & 63;
        if (bufsel == 0) {
            uint32_t* base = qs2 + i * S2Q + h * 16;
            uint4 r[4];
            float ssq = 0.f;
#pragma unroll
            for (int u = 0; u < 4; ++u) {
                r[u] = ((uint4*)base)[u];
                float2 f0 = uph2(r[u].x), f1 = uph2(r[u].y);
                float2 f2 = uph2(r[u].z), f3 = uph2(r[u].w);
                ssq += f0.x * f0.x + f0.y * f0.y + f1.x * f1.x + f1.y * f1.y
                     + f2.x * f2.x + f2.y * f2.y + f3.x * f3.x + f3.y * f3.y;
            }
            float inv = fminf(expf(ls[s * 4 + h]), 100.f) / fmaxf(sqrtf(ssq), 1e-12f);
#pragma unroll
            for (int u = 0; u < 4; ++u) {
                uint4 w;
                float2 f0 = uph2(r[u].x), f1 = uph2(r[u].y);
                float2 f2 = uph2(r[u].z), f3 = uph2(r[u].w);
                w.x = pkh2(f0.x * inv, f0.y * inv);
                w.y = pkh2(f1.x * inv, f1.y * inv);
                w.z = pkh2(f2.x * inv, f2.y * inv);
                w.w = pkh2(f3.x * inv, f3.y * inv);
                ((uint4*)base)[u] = w;
            }
        } else {
            uint32_t r[16];
            float ssq = 0.f;
#pragma unroll
            for (int kk = 0; kk < 16; ++kk) {
                r[kk] = kbufU[(h * 16 + kk) * S2K + i];
                float2 f = uph2(r[kk]);
                ssq += f.x * f.x + f.y * f.y;
            }
            float inv = 1.f / fmaxf(sqrtf(ssq), 1e-12f);
#pragma unroll
            for (int kk = 0; kk < 16; ++kk) {
                float2 f = uph2(r[kk]);
                kbufU[(h * 16 + kk) * S2K + i] = pkh2(f.x * inv, f.y * inv);
            }
        }
    }
    __syncthreads();                         // B6

    // =========== Phase 3: attention (fp16 mma), two warps per head ===========
    {
        const int h = warp >> 1;
        const int mtb = (warp & 1) * 2;
        const float* Tw = d_Tcomb +
            (size_t)((((win & (NWIN - 1)) * NHEADS + s * 4 + h)) << 12);

#pragma unroll 1
        for (int mm = 0; mm < 2; ++mm) {
            const int i0r = (mtb + mm) * 16 + qr;

            uint32_t qa[2][4];
#pragma unroll
            for (int kt = 0; kt < 2; ++kt) {
                const uint32_t* ap = qs2 + i0r * S2Q + h * 16 + kt * 8 + ql;
                qa[kt][0] = ap[0];
                qa[kt][1] = ap[8 * S2Q];
                qa[kt][2] = ap[4];
                qa[kt][3] = ap[8 * S2Q + 4];
            }

            float S[8][4];
#pragma unroll
            for (int nt = 0; nt < 8; ++nt) { S[nt][0] = S[nt][1] = S[nt][2] = S[nt][3] = 0.f; }
#pragma unroll
            for (int kt = 0; kt < 2; ++kt) {
                const uint32_t* bp = kbufU + (h * 16 + kt * 8 + ql) * S2K + qr;
#pragma unroll
                for (int nt = 0; nt < 8; ++nt) {
                    mma_f16(S[nt][0], S[nt][1], S[nt][2], S[nt][3],
                            qa[kt][0], qa[kt][1], qa[kt][2], qa[kt][3],
                            bp[nt * 8], bp[4 * S2K + nt * 8]);
                }
            }

            float rmax0 = -1e30f, rmax1 = -1e30f;
#pragma unroll
            for (int nt = 0; nt < 8; ++nt) {
                float2 t0 = *(const float2*)&Tw[i0r * 64 + nt * 8 + 2 * ql];
                float2 t1 = *(const float2*)&Tw[(i0r + 8) * 64 + nt * 8 + 2 * ql];
                S[nt][0] += t0.x; S[nt][1] += t0.y;
                S[nt][2] += t1.x; S[nt][3] += t1.y;
                rmax0 = fmaxf(rmax0, fmaxf(S[nt][0], S[nt][1]));
                rmax1 = fmaxf(rmax1, fmaxf(S[nt][2], S[nt][3]));
            }
            rmax0 = fmaxf(rmax0, __shfl_xor_sync(0xffffffffu, rmax0, 1));
            rmax0 = fmaxf(rmax0, __shfl_xor_sync(0xffffffffu, rmax0, 2));
            rmax1 = fmaxf(rmax1, __shfl_xor_sync(0xffffffffu, rmax1, 1));
            rmax1 = fmaxf(rmax1, __shfl_xor_sync(0xffffffffu, rmax1, 2));

            float sum0 = 0.f, sum1 = 0.f;
#pragma unroll
            for (int nt = 0; nt < 8; ++nt) {
                S[nt][0] = __expf(S[nt][0] - rmax0); sum0 += S[nt][0];
                S[nt][1] = __expf(S[nt][1] - rmax0); sum0 += S[nt][1];
                S[nt][2] = __expf(S[nt][2] - rmax1); sum1 += S[nt][2];
                S[nt][3] = __expf(S[nt][3] - rmax1); sum1 += S[nt][3];
            }
            sum0 += __shfl_xor_sync(0xffffffffu, sum0, 1);
            sum0 += __shfl_xor_sync(0xffffffffu, sum0, 2);
            sum1 += __shfl_xor_sync(0xffffffffu, sum1, 1);
            sum1 += __shfl_xor_sync(0xffffffffu, sum1, 2);
            float inv0 = 1.f / sum0, inv1 = 1.f / sum1;

            // P -> A-fragments: fp16 C/A layouts coincide, no shuffles
            uint32_t pa[4][4];
#pragma unroll
            for (int kt = 0; kt < 4; ++kt) {
                pa[kt][0] = pkh2(S[2 * kt][0] * inv0, S[2 * kt][1] * inv0);
                pa[kt][1] = pkh2(S[2 * kt][2] * inv1, S[2 * kt][3] * inv1);
                pa[kt][2] = pkh2(S[2 * kt + 1][0] * inv0, S[2 * kt + 1][1] * inv0);
                pa[kt][3] = pkh2(S[2 * kt + 1][2] * inv1, S[2 * kt + 1][3] * inv1);
            }

            float O[4][4];
#pragma unroll
            for (int nd = 0; nd < 4; ++nd) { O[nd][0] = O[nd][1] = O[nd][2] = O[nd][3] = 0.f; }
#pragma unroll
            for (int kt = 0; kt < 4; ++kt) {
                const uint32_t* vp = vbufU + (kt * 8 + ql) * S2V + h * 32 + qr;
#pragma unroll
                for (int nd = 0; nd < 4; ++nd) {
                    mma_f16(O[nd][0], O[nd][1], O[nd][2], O[nd][3],
                            pa[kt][0], pa[kt][1], pa[kt][2], pa[kt][3],
                            vp[nd * 8], vp[4 * S2V + nd * 8]);
                }
            }

            // O (already normalized) -> fp16 pairs into qs
#pragma unroll
            for (int nd = 0; nd < 4; ++nd) {
                qs2[i0r * S2Q + h * 16 + nd * 4 + ql] = pkh2(O[nd][0], O[nd][1]);
                qs2[(i0r + 8) * S2Q + h * 16 + nd * 4 + ql] = pkh2(O[nd][2], O[nd][3]);
            }
        }
    }
    WAITSYNC();                              // B7: phase-3 writes visible + P weights landed

    // =========== Phase 4: output projection ===========
    float* og = out + (size_t)win * (NTOK * CDIM);
    {
        float acc[2][4][4];
        ZERO_ACC(acc);
        LOAD_AF_H(0);
        MMA_LOOP(wstA, acc, 0);
        LOAD_AF_H(1);
        MMA_LOOP(wstB, acc, 1);

#pragma unroll
        for (int mt = 0; mt < 2; ++mt) {
            const int rr = r0 + mt * 16 + qr;
#pragma unroll
            for (int nt = 0; nt < 4; ++nt) {
                const int c = n0 + nt * 8 + 2 * ql;
                float2 pb2 = *(const float2*)&pb[s * 128 + c];
                *(float2*)&og[rr * CDIM + s * 128 + c] =
                    make_float2(acc[mt][nt][0] + pb2.x, acc[mt][nt][1] + pb2.y);
                *(float2*)&og[(rr + 8) * CDIM + s * 128 + c] =
                    make_float2(acc[mt][nt][2] + pb2.x, acc[mt][nt][3] + pb2.y);
            }
        }
    }
}

extern "C" void kernel_launch(void* const* d_in, const int* in_sizes, int n_in,
                              void* d_out, int out_size) {
    const float* x    = (const float*)d_in[0];
    const float* mask = (const float*)d_in[1];
    const float* qw   = (const float*)d_in[2];
    const float* qb   = (const float*)d_in[3];
    const float* kw   = (const float*)d_in[4];
    const float* kb   = (const float*)d_in[5];
    const float* vw   = (const float*)d_in[6];
    const float* vb   = (const float*)d_in[7];
    const float* pw   = (const float*)d_in[8];
    const float* pb   = (const float*)d_in[9];
    const float* w1   = (const float*)d_in[10];
    const float* b1   = (const float*)d_in[11];
    const float* w2   = (const float*)d_in[12];
    const float* ls   = (const float*)d_in[13];
    const float* rpb  = (const float*)d_in[14];
    const int*   rpi  = (const int*)d_in[15];
    float* out = (float*)d_out;

    static bool inited = false;
    if (!inited) {
        cudaFuncSetAttribute(swin_branch_kernel,
                             cudaFuncAttributeMaxDynamicSharedMemorySize, SMEM_BYTES);
        inited = true;
    }

    prologue_kernel<<<737, 256>>>(qw, kw, vw, pw, rpb, w1, b1, w2);
    bias_combine_kernel<<<(NWIN * NHEADS * NTOK * NTOK + 255) / 256, 256>>>(rpi, mask);
    swin_branch_kernel<<<NBATCH * 2, THREADS, SMEM_BYTES>>>(x, qb, kb, vb, pb, ls, out);
}

// round 16
// speedup vs baseline: 1.0561x; 1.0561x over previous
#include <cuda_runtime.h>
#include <cuda_fp16.h>
#include <math.h>
#include <stdint.h>

#define NTOK 64
#define CDIM 256
#define NHEADS 8
#define HD   32
#define NWIN 64
#define NBATCH 2048
#define THREADS 256

// strides in uint32 (half2) units
#define S2Q 68            // qs: 4 mod 32 -> conflict-free qr-row access
#define S2K 72            // kbuf: 8 mod 32 -> conflict-free ql-row access
#define S2V 136           // vbuf: 8 mod 32
#define S2W 136           // weight stages: 8 mod 32

// smem layout (uint32 units)
#define OFF_Q  0                        // 64 x 68
#define OFF_K  (64 * S2Q)               // 64 x 72
#define OFF_V  (OFF_K + 64 * S2K)       // 32 x 136
#define OFF_WA (OFF_V + 32 * S2V)       // 32 x 136
#define OFF_WB (OFF_WA + 32 * S2W)      // 32 x 136
#define SMEM_U32 (OFF_WB + 32 * S2W)
#define SMEM_BYTES (SMEM_U32 * 4)       // 88064 B -> 2 CTAs/SM

__device__ float d_tbl2[225 * NHEADS];
__device__ float d_Tcomb[NWIN * NHEADS * NTOK * NTOK];   // 16*sigmoid(bias)+mask, 8MB
__device__ uint32_t d_wh[4 * 2 * 2 * 32 * 128];          // fp16 k-pair packed weights

// ---------------- helpers ----------------
__device__ __forceinline__ uint32_t pkh2(float a, float b) {
    __half2 h = __floats2half2_rn(a, b);
    return *reinterpret_cast<uint32_t*>(&h);
}
__device__ __forceinline__ float2 uph2(uint32_t u) {
    __half2 h = *reinterpret_cast<__half2*>(&u);
    return __half22float2(h);
}

// ---------------- fused prologue: weight pack (blocks 0..511) + CPB MLP (512..736) ----------------
__global__ void prologue_kernel(const float* __restrict__ qw, const float* __restrict__ kw,
                                const float* __restrict__ vw, const float* __restrict__ pw,
                                const float* __restrict__ rpb, const float* __restrict__ w1,
                                const float* __restrict__ b1, const float* __restrict__ w2) {
    if (blockIdx.x < 512) {
        int idx = blockIdx.x * 256 + threadIdx.x;    // < 131072
        int w  = idx >> 14;
        int s  = (idx >> 13) & 1;
        int hf = (idx >> 12) & 1;
        int kk = (idx >> 7) & 31;
        int n  = idx & 127;
        const float* src = (w == 0) ? qw : (w == 1) ? kw : (w == 2) ? vw : pw;
        int c = hf * 64 + 2 * kk;
        float v0 = src[s * 16384 + c * 128 + n];
        float v1 = src[s * 16384 + (c + 1) * 128 + n];
        d_wh[idx] = pkh2(v0, v1);
    } else {
        __shared__ float acc[NHEADS];
        int p = blockIdx.x - 512;                    // 0..224
        int j = threadIdx.x;                         // 0..255; hidden dim is 128
        if (j < NHEADS) acc[j] = 0.f;
        __syncthreads();
        float t0 = rpb[p * 2 + 0];
        float t1 = rpb[p * 2 + 1];
        float hid = 0.f;
        if (j < 128) hid = fmaxf(t0 * w1[j] + t1 * w1[128 + j] + b1[j], 0.f);
#pragma unroll
        for (int h = 0; h < NHEADS; ++h) {
            float pv = (j < 128) ? hid * w2[j * 8 + h] : 0.f;
#pragma unroll
            for (int o = 16; o; o >>= 1) pv += __shfl_xor_sync(0xffffffffu, pv, o);
            if ((j & 31) == 0) atomicAdd(&acc[h], pv);
        }
        __syncthreads();
        if (j < NHEADS) d_tbl2[p * 8 + j] = acc[j];
    }
}

// ---------------- prologue 2: combined bias+mask table ----------------
__global__ void bias_combine_kernel(const int* __restrict__ rpi,
                                    const float* __restrict__ mask) {
    int idx = blockIdx.x * blockDim.x + threadIdx.x;
    if (idx >= NWIN * NHEADS * NTOK * NTOK) return;
    int ij = idx & 4095;
    int h  = (idx >> 12) & 7;
    int w  = idx >> 15;
    float bv = d_tbl2[rpi[ij] * 8 + h];
    d_Tcomb[idx] = 16.f / (1.f + expf(-bv)) + mask[w * 4096 + ij];
}

// ---------------- fp16 mma m16n8k16 ----------------
__device__ __forceinline__ void mma_f16(float& d0, float& d1, float& d2, float& d3,
                                        uint32_t a0, uint32_t a1, uint32_t a2, uint32_t a3,
                                        uint32_t b0, uint32_t b1) {
    asm volatile(
        "mma.sync.aligned.m16n8k16.row.col.f32.f16.f16.f32 "
        "{%0,%1,%2,%3},{%4,%5,%6,%7},{%8,%9},{%0,%1,%2,%3};"
        : "+f"(d0), "+f"(d1), "+f"(d2), "+f"(d3)
        : "r"(a0), "r"(a1), "r"(a2), "r"(a3), "r"(b0), "r"(b1));
}

// weight source: w 0..3 = q,k,v,p; half hf -> [32 kk][128 n] uint32 block
#define WSRC(w, hf) (d_wh + (((w) * 2 + s) * 2 + (hf)) * 4096)

// stage one [32 kk][128 n] uint32 weight half via 4 cp.async per thread
#define ISSUE(SRC, DSTU) do {                                                \
    const uint32_t* _s0 = (SRC) + ldrow * 128 + ldcol;                       \
    uint32_t _d0 = (DSTU) + (uint32_t)((ldrow * S2W + ldcol) * 4);           \
    _Pragma("unroll")                                                        \
    for (int k_ = 0; k_ < 4; ++k_)                                           \
        asm volatile("cp.async.cg.shared.global [%0], [%1], 16;\n"           \
            :: "r"(_d0 + (uint32_t)(k_ * 8 * S2W * 4)),                      \
               "l"(_s0 + k_ * 8 * 128) : "memory");                          \
    asm volatile("cp.async.commit_group;\n" ::: "memory");                   \
} while (0)

#define WAITSYNC() do {                                                      \
    asm volatile("cp.async.wait_group 0;\n" ::: "memory");                   \
    __syncthreads();                                                         \
} while (0)

// 32x32 warp-tile fp16 mma over one staged weight half, A from af[AH]
#define MMA_LOOP(BUFU, ACC, AH) do {                                         \
    const uint32_t* _bu = (BUFU);                                            \
    _Pragma("unroll")                                                        \
    for (int kt = 0; kt < 4; ++kt) {                                         \
        const uint32_t* bp = _bu + (kt * 8 + ql) * S2W + n0 + qr;            \
        _Pragma("unroll")                                                    \
        for (int nt = 0; nt < 4; ++nt) {                                     \
            uint32_t b0_ = bp[nt * 8], b1_ = bp[4 * S2W + nt * 8];           \
            mma_f16(ACC[0][nt][0], ACC[0][nt][1], ACC[0][nt][2], ACC[0][nt][3], \
                    af[AH][0][kt][0], af[AH][0][kt][1], af[AH][0][kt][2], af[AH][0][kt][3], \
                    b0_, b1_);                                               \
            mma_f16(ACC[1][nt][0], ACC[1][nt][1], ACC[1][nt][2], ACC[1][nt][3], \
                    af[AH][1][kt][0], af[AH][1][kt][1], af[AH][1][kt][2], af[AH][1][kt][3], \
                    b0_, b1_);                                               \
        }                                                                    \
    }                                                                        \
} while (0)

// load A fragments for half HF into af[HF] (2 row tiles x 4 k16 tiles)
#define LOAD_AF_H(HF) do {                                                   \
    _Pragma("unroll")                                                        \
    for (int mt = 0; mt < 2; ++mt)                                           \
    _Pragma("unroll")                                                        \
    for (int kt = 0; kt < 4; ++kt) {                                         \
        const uint32_t* ap = qs2 + (r0 + mt * 16 + qr) * S2Q + (HF) * 32 + kt * 8 + ql; \
        af[HF][mt][kt][0] = ap[0];                                           \
        af[HF][mt][kt][1] = ap[8 * S2Q];                                     \
        af[HF][mt][kt][2] = ap[4];                                           \
        af[HF][mt][kt][3] = ap[8 * S2Q + 4];                                 \
    }                                                                        \
} while (0)

#define ZERO_ACC(A) do {                                                     \
    _Pragma("unroll")                                                        \
    for (int mt = 0; mt < 2; ++mt)                                           \
    _Pragma("unroll")                                                        \
    for (int nt = 0; nt < 4; ++nt)                                           \
        { A[mt][nt][0] = 0.f; A[mt][nt][1] = 0.f; A[mt][nt][2] = 0.f; A[mt][nt][3] = 0.f; } \
} while (0)

// ---------------- main fused kernel: one CTA per (window, branch) ----------------
__global__ void __launch_bounds__(THREADS, 2)
swin_branch_kernel(const float* __restrict__ x,
                   const float* __restrict__ qb, const float* __restrict__ kb,
                   const float* __restrict__ vb, const float* __restrict__ pb,
                   const float* __restrict__ ls, float* __restrict__ out)
{
    extern __shared__ uint32_t smU[];
    uint32_t* qs2   = smU + OFF_Q;    // x / q / O as fp16 pairs (64 x 68)
    uint32_t* kbufU = smU + OFF_K;    // K d-pair transposed [d/2=64][key 64] (stride 72)
    uint32_t* vbufU = smU + OFF_V;    // V token-pair [tok/2=32][d 128] (stride 136)
    uint32_t* wstA  = smU + OFF_WA;
    uint32_t* wstB  = smU + OFF_WB;

    const int bid  = blockIdx.x;
    const int win  = bid >> 1;
    const int s    = bid & 1;               // branch (heads s*4..s*4+3)
    const int tid  = threadIdx.x;
    const int warp = tid >> 5;
    const int lane = tid & 31;
    const int r0   = (warp & 1) * 32;       // 32x32 warp tiles: 2 row x 4 col grid
    const int n0   = (warp >> 1) * 32;      // col tile == one head
    const int qr   = lane >> 2;
    const int ql   = lane & 3;
    const int ldrow = tid >> 5;             // staging row base 0..7
    const int ldcol = (tid & 31) * 4;       // staging col (uint32) 0..124

    const uint32_t wA_u = (uint32_t)__cvta_generic_to_shared(wstA);
    const uint32_t wB_u = (uint32_t)__cvta_generic_to_shared(wstB);

    uint32_t af[2][2][4][4];                // A frags, both halves, held across K/V/Q

    ISSUE(WSRC(1, 0), wA_u);               // prefetch K weights half 0

    // per-warp head logit scale (used in Q epilogue normalization)
    const float qscale = fminf(expf(ls[s * 4 + (warp >> 1)]), 100.f);

    // load x branch slice [64][128] -> fp16 pairs in qs
    const float4* xg4 = (const float4*)(x + (size_t)win * (NTOK * CDIM));
    for (int t = tid; t < 64 * 32; t += THREADS) {
        int i = t >> 5, j = t & 31;
        float4 v = xg4[i * 64 + s * 32 + j];
        uint2 st; st.x = pkh2(v.x, v.y); st.y = pkh2(v.z, v.w);
        *(uint2*)&qs2[i * S2Q + j * 2] = st;
    }
    __syncthreads();

    LOAD_AF_H(0);
    LOAD_AF_H(1);

    // =========== Phase 1: K, V, Q residual linears (single live acc set) ===========
    {
        // --- K GEMM ---
        float acc[2][4][4];
        ZERO_ACC(acc);
        WAITSYNC(); ISSUE(WSRC(1, 1), wB_u);
        MMA_LOOP(wstA, acc, 0);
        WAITSYNC(); ISSUE(WSRC(2, 0), wA_u);
        MMA_LOOP(wstB, acc, 1);

        // k epilogue: in-place acc = x+acc+kb, quad-reduce row norms (fp32),
        // store NORMALIZED fp16 pairs -> kbuf d-pair transposed [c/2][key]
#pragma unroll
        for (int mt = 0; mt < 2; ++mt) {
            const int rr = r0 + mt * 16 + qr;
            float ssq0 = 0.f, ssq1 = 0.f;
#pragma unroll
            for (int nt = 0; nt < 4; ++nt) {
                const int c = n0 + nt * 8 + 2 * ql;
                float2 x0 = uph2(qs2[rr * S2Q + (c >> 1)]);
                float2 x1 = uph2(qs2[(rr + 8) * S2Q + (c >> 1)]);
                float2 kb2 = *(const float2*)&kb[s * 128 + c];
                acc[mt][nt][0] = x0.x + acc[mt][nt][0] + kb2.x;
                acc[mt][nt][1] = x0.y + acc[mt][nt][1] + kb2.y;
                acc[mt][nt][2] = x1.x + acc[mt][nt][2] + kb2.x;
                acc[mt][nt][3] = x1.y + acc[mt][nt][3] + kb2.y;
                ssq0 = fmaf(acc[mt][nt][0], acc[mt][nt][0], fmaf(acc[mt][nt][1], acc[mt][nt][1], ssq0));
                ssq1 = fmaf(acc[mt][nt][2], acc[mt][nt][2], fmaf(acc[mt][nt][3], acc[mt][nt][3], ssq1));
            }
            ssq0 += __shfl_xor_sync(0xffffffffu, ssq0, 1);
            ssq0 += __shfl_xor_sync(0xffffffffu, ssq0, 2);
            ssq1 += __shfl_xor_sync(0xffffffffu, ssq1, 1);
            ssq1 += __shfl_xor_sync(0xffffffffu, ssq1, 2);
            float inv0 = 1.f / fmaxf(sqrtf(ssq0), 1e-12f);
            float inv1 = 1.f / fmaxf(sqrtf(ssq1), 1e-12f);
#pragma unroll
            for (int nt = 0; nt < 4; ++nt) {
                const int c = n0 + nt * 8 + 2 * ql;
                kbufU[(c >> 1) * S2K + rr] =
                    pkh2(acc[mt][nt][0] * inv0, acc[mt][nt][1] * inv0);
                kbufU[(c >> 1) * S2K + rr + 8] =
                    pkh2(acc[mt][nt][2] * inv1, acc[mt][nt][3] * inv1);
            }
        }
    }
    {
        // --- V GEMM ---
        float acc[2][4][4];
        ZERO_ACC(acc);
        WAITSYNC(); ISSUE(WSRC(2, 1), wB_u);
        MMA_LOOP(wstA, acc, 0);
        WAITSYNC(); ISSUE(WSRC(0, 0), wA_u);
        MMA_LOOP(wstB, acc, 1);

        // v epilogue: token-pair pack via lane-xor-4 exchange -> vbuf
#pragma unroll
        for (int mt = 0; mt < 2; ++mt) {
            const int rr = r0 + mt * 16 + qr;
            const int m0 = rr >> 1;
            const uint32_t psel = (qr & 1) ? 0x3276u : 0x5410u;
            const int cofs = (qr & 1);
#pragma unroll
            for (int nt = 0; nt < 4; ++nt) {
                const int c = n0 + nt * 8 + 2 * ql;
                float2 x0 = uph2(qs2[rr * S2Q + (c >> 1)]);
                float2 x1 = uph2(qs2[(rr + 8) * S2Q + (c >> 1)]);
                float2 vb2 = *(const float2*)&vb[s * 128 + c];
                uint32_t mine0 = pkh2(x0.x + acc[mt][nt][0] + vb2.x, x0.y + acc[mt][nt][1] + vb2.y);
                uint32_t mine1 = pkh2(x1.x + acc[mt][nt][2] + vb2.x, x1.y + acc[mt][nt][3] + vb2.y);
                uint32_t oth0 = __shfl_xor_sync(0xffffffffu, mine0, 4);
                uint32_t oth1 = __shfl_xor_sync(0xffffffffu, mine1, 4);
                vbufU[m0 * S2V + c + cofs]       = __byte_perm(mine0, oth0, psel);
                vbufU[(m0 + 4) * S2V + c + cofs] = __byte_perm(mine1, oth1, psel);
            }
        }
    }
    {
        // --- Q GEMM (epilogue overwrites x in qs, NORMALIZED with scale) ---
        float acc[2][4][4];
        ZERO_ACC(acc);
        WAITSYNC(); ISSUE(WSRC(0, 1), wB_u);
        MMA_LOOP(wstA, acc, 0);
        WAITSYNC(); ISSUE(WSRC(3, 0), wA_u);   // P weights h0
        MMA_LOOP(wstB, acc, 1);

#pragma unroll
        for (int mt = 0; mt < 2; ++mt) {
            const int rr = r0 + mt * 16 + qr;
            float ssq0 = 0.f, ssq1 = 0.f;
#pragma unroll
            for (int nt = 0; nt < 4; ++nt) {
                const int c = n0 + nt * 8 + 2 * ql;
                float2 x0 = uph2(qs2[rr * S2Q + (c >> 1)]);
                float2 x1 = uph2(qs2[(rr + 8) * S2Q + (c >> 1)]);
                float2 qb2 = *(const float2*)&qb[s * 128 + c];
                acc[mt][nt][0] = x0.x + acc[mt][nt][0] + qb2.x;
                acc[mt][nt][1] = x0.y + acc[mt][nt][1] + qb2.y;
                acc[mt][nt][2] = x1.x + acc[mt][nt][2] + qb2.x;
                acc[mt][nt][3] = x1.y + acc[mt][nt][3] + qb2.y;
                ssq0 = fmaf(acc[mt][nt][0], acc[mt][nt][0], fmaf(acc[mt][nt][1], acc[mt][nt][1], ssq0));
                ssq1 = fmaf(acc[mt][nt][2], acc[mt][nt][2], fmaf(acc[mt][nt][3], acc[mt][nt][3], ssq1));
            }
            ssq0 += __shfl_xor_sync(0xffffffffu, ssq0, 1);
            ssq0 += __shfl_xor_sync(0xffffffffu, ssq0, 2);
            ssq1 += __shfl_xor_sync(0xffffffffu, ssq1, 1);
            ssq1 += __shfl_xor_sync(0xffffffffu, ssq1, 2);
            float inv0 = qscale / fmaxf(sqrtf(ssq0), 1e-12f);
            float inv1 = qscale / fmaxf(sqrtf(ssq1), 1e-12f);
#pragma unroll
            for (int nt = 0; nt < 4; ++nt) {
                const int c = n0 + nt * 8 + 2 * ql;
                qs2[rr * S2Q + (c >> 1)] =
                    pkh2(acc[mt][nt][0] * inv0, acc[mt][nt][1] * inv0);
                qs2[(rr + 8) * S2Q + (c >> 1)] =
                    pkh2(acc[mt][nt][2] * inv1, acc[mt][nt][3] * inv1);
            }
        }
    }
    __syncthreads();           // k (cross-warp) + q visible for phase 3
    ISSUE(WSRC(3, 1), wB_u);   // P weights h1 (wstB reads complete: all warps past sync)

    // =========== Phase 3: attention (fp16 mma), two warps per head ===========
    {
        const int h = warp >> 1;
        const int mtb = (warp & 1) * 2;
        const float* Tw = d_Tcomb +
            (size_t)((((win & (NWIN - 1)) * NHEADS + s * 4 + h)) << 12);

#pragma unroll 1
        for (int mm = 0; mm < 2; ++mm) {
            const int i0r = (mtb + mm) * 16 + qr;

            uint32_t qa[2][4];
#pragma unroll
            for (int kt = 0; kt < 2; ++kt) {
                const uint32_t* ap = qs2 + i0r * S2Q + h * 16 + kt * 8 + ql;
                qa[kt][0] = ap[0];
                qa[kt][1] = ap[8 * S2Q];
                qa[kt][2] = ap[4];
                qa[kt][3] = ap[8 * S2Q + 4];
            }

            float S[8][4];
#pragma unroll
            for (int nt = 0; nt < 8; ++nt) { S[nt][0] = S[nt][1] = S[nt][2] = S[nt][3] = 0.f; }
#pragma unroll
            for (int kt = 0; kt < 2; ++kt) {
                const uint32_t* bp = kbufU + (h * 16 + kt * 8 + ql) * S2K + qr;
#pragma unroll
                for (int nt = 0; nt < 8; ++nt) {
                    mma_f16(S[nt][0], S[nt][1], S[nt][2], S[nt][3],
                            qa[kt][0], qa[kt][1], qa[kt][2], qa[kt][3],
                            bp[nt * 8], bp[4 * S2K + nt * 8]);
                }
            }

            float rmax0 = -1e30f, rmax1 = -1e30f;
#pragma unroll
            for (int nt = 0; nt < 8; ++nt) {
                float2 t0 = *(const float2*)&Tw[i0r * 64 + nt * 8 + 2 * ql];
                float2 t1 = *(const float2*)&Tw[(i0r + 8) * 64 + nt * 8 + 2 * ql];
                S[nt][0] += t0.x; S[nt][1] += t0.y;
                S[nt][2] += t1.x; S[nt][3] += t1.y;
                rmax0 = fmaxf(rmax0, fmaxf(S[nt][0], S[nt][1]));
                rmax1 = fmaxf(rmax1, fmaxf(S[nt][2], S[nt][3]));
            }
            rmax0 = fmaxf(rmax0, __shfl_xor_sync(0xffffffffu, rmax0, 1));
            rmax0 = fmaxf(rmax0, __shfl_xor_sync(0xffffffffu, rmax0, 2));
            rmax1 = fmaxf(rmax1, __shfl_xor_sync(0xffffffffu, rmax1, 1));
            rmax1 = fmaxf(rmax1, __shfl_xor_sync(0xffffffffu, rmax1, 2));

            float sum0 = 0.f, sum1 = 0.f;
#pragma unroll
            for (int nt = 0; nt < 8; ++nt) {
                S[nt][0] = __expf(S[nt][0] - rmax0); sum0 += S[nt][0];
                S[nt][1] = __expf(S[nt][1] - rmax0); sum0 += S[nt][1];
                S[nt][2] = __expf(S[nt][2] - rmax1); sum1 += S[nt][2];
                S[nt][3] = __expf(S[nt][3] - rmax1); sum1 += S[nt][3];
            }
            sum0 += __shfl_xor_sync(0xffffffffu, sum0, 1);
            sum0 += __shfl_xor_sync(0xffffffffu, sum0, 2);
            sum1 += __shfl_xor_sync(0xffffffffu, sum1, 1);
            sum1 += __shfl_xor_sync(0xffffffffu, sum1, 2);
            float inv0 = 1.f / sum0, inv1 = 1.f / sum1;

            // P -> A-fragments: fp16 C/A layouts coincide, no shuffles
            uint32_t pa[4][4];
#pragma unroll
            for (int kt = 0; kt < 4; ++kt) {
                pa[kt][0] = pkh2(S[2 * kt][0] * inv0, S[2 * kt][1] * inv0);
                pa[kt][1] = pkh2(S[2 * kt][2] * inv1, S[2 * kt][3] * inv1);
                pa[kt][2] = pkh2(S[2 * kt + 1][0] * inv0, S[2 * kt + 1][1] * inv0);
                pa[kt][3] = pkh2(S[2 * kt + 1][2] * inv1, S[2 * kt + 1][3] * inv1);
            }

            float O[4][4];
#pragma unroll
            for (int nd = 0; nd < 4; ++nd) { O[nd][0] = O[nd][1] = O[nd][2] = O[nd][3] = 0.f; }
#pragma unroll
            for (int kt = 0; kt < 4; ++kt) {
                const uint32_t* vp = vbufU + (kt * 8 + ql) * S2V + h * 32 + qr;
#pragma unroll
                for (int nd = 0; nd < 4; ++nd) {
                    mma_f16(O[nd][0], O[nd][1], O[nd][2], O[nd][3],
                            pa[kt][0], pa[kt][1], pa[kt][2], pa[kt][3],
                            vp[nd * 8], vp[4 * S2V + nd * 8]);
                }
            }

            // O (already normalized) -> fp16 pairs into qs
#pragma unroll
            for (int nd = 0; nd < 4; ++nd) {
                qs2[i0r * S2Q + h * 16 + nd * 4 + ql] = pkh2(O[nd][0], O[nd][1]);
                qs2[(i0r + 8) * S2Q + h * 16 + nd * 4 + ql] = pkh2(O[nd][2], O[nd][3]);
            }
        }
    }
    WAITSYNC();                // phase-3 writes visible + P weights landed

    // =========== Phase 4: output projection (P weights already staged) ===========
    float* og = out + (size_t)win * (NTOK * CDIM);
    {
        float acc[2][4][4];
        ZERO_ACC(acc);
        LOAD_AF_H(0);
        MMA_LOOP(wstA, acc, 0);
        LOAD_AF_H(1);
        MMA_LOOP(wstB, acc, 1);

#pragma unroll
        for (int mt = 0; mt < 2; ++mt) {
            const int rr = r0 + mt * 16 + qr;
#pragma unroll
            for (int nt = 0; nt < 4; ++nt) {
                const int c = n0 + nt * 8 + 2 * ql;
                float2 pb2 = *(const float2*)&pb[s * 128 + c];
                *(float2*)&og[rr * CDIM + s * 128 + c] =
                    make_float2(acc[mt][nt][0] + pb2.x, acc[mt][nt][1] + pb2.y);
                *(float2*)&og[(rr + 8) * CDIM + s * 128 + c] =
                    make_float2(acc[mt][nt][2] + pb2.x, acc[mt][nt][3] + pb2.y);
            }
        }
    }
}

extern "C" void kernel_launch(void* const* d_in, const int* in_sizes, int n_in,
                              void* d_out, int out_size) {
    const float* x    = (const float*)d_in[0];
    const float* mask = (const float*)d_in[1];
    const float* qw   = (const float*)d_in[2];
    const float* qb   = (const float*)d_in[3];
    const float* kw   = (const float*)d_in[4];
    const float* kb   = (const float*)d_in[5];
    const float* vw   = (const float*)d_in[6];
    const float* vb   = (const float*)d_in[7];
    const float* pw   = (const float*)d_in[8];
    const float* pb   = (const float*)d_in[9];
    const float* w1   = (const float*)d_in[10];
    const float* b1   = (const float*)d_in[11];
    const float* w2   = (const float*)d_in[12];
    const float* ls   = (const float*)d_in[13];
    const float* rpb  = (const float*)d_in[14];
    const int*   rpi  = (const int*)d_in[15];
    float* out = (float*)d_out;

    static bool inited = false;
    if (!inited) {
        cudaFuncSetAttribute(swin_branch_kernel,
                             cudaFuncAttributeMaxDynamicSharedMemorySize, SMEM_BYTES);
        inited = true;
    }

    prologue_kernel<<<737, 256>>>(qw, kw, vw, pw, rpb, w1, b1, w2);
    bias_combine_kernel<<<(NWIN * NHEADS * NTOK * NTOK + 255) / 256, 256>>>(rpi, mask);
    swin_branch_kernel<<<NBATCH * 2, THREADS, SMEM_BYTES>>>(x, qb, kb, vb, pb, ls, out);
}

// round 17
// speedup vs baseline: 1.2170x; 1.1524x over previous
#include <cuda_runtime.h>
#include <cuda_fp16.h>
#include <math.h>
#include <stdint.h>

#define NTOK 64
#define CDIM 256
#define NHEADS 8
#define HD   32
#define NWIN 64
#define NBATCH 2048
#define THREADS 256

// strides in uint32 (half2) units
#define S2Q 68            // qs: 4 mod 32 -> conflict-free qr-row access
#define S2K 72            // kbuf: 8 mod 32 -> conflict-free ql-row access
#define S2V 136           // vbuf: 8 mod 32
#define S2W 136           // weight stages: 8 mod 32

// smem layout (uint32 units) — 3 CTAs/SM budget
#define OFF_Q  0                        // 64 x 68  = 4352
#define OFF_K  (64 * S2Q)               // 64 x 72  = 4608
#define OFF_V  (OFF_K + 64 * S2K)       // 32 x 136 = 4352 (v data / stage overlay)
#define OFF_W  (OFF_V + 32 * S2V)       // 32 x 136 = 4352 (dedicated stage)
#define SMEM_U32 (OFF_W + 32 * S2W)     // 17664
#define SMEM_BYTES (SMEM_U32 * 4)       // 70656 B -> 3 CTAs/SM

__device__ float d_tbl2[225 * NHEADS];
__device__ float d_Tcomb[NWIN * NHEADS * NTOK * NTOK];   // 16*sigmoid(bias)+mask, 8MB
__device__ uint32_t d_wh[4 * 2 * 2 * 32 * 128];          // fp16 k-pair packed weights

// ---------------- helpers ----------------
__device__ __forceinline__ uint32_t pkh2(float a, float b) {
    __half2 h = __floats2half2_rn(a, b);
    return *reinterpret_cast<uint32_t*>(&h);
}
__device__ __forceinline__ float2 uph2(uint32_t u) {
    __half2 h = *reinterpret_cast<__half2*>(&u);
    return __half22float2(h);
}

// ---------------- fused prologue: weight pack (blocks 0..511) + CPB MLP (512..736) ----------------
__global__ void prologue_kernel(const float* __restrict__ qw, const float* __restrict__ kw,
                                const float* __restrict__ vw, const float* __restrict__ pw,
                                const float* __restrict__ rpb, const float* __restrict__ w1,
                                const float* __restrict__ b1, const float* __restrict__ w2) {
    if (blockIdx.x < 512) {
        int idx = blockIdx.x * 256 + threadIdx.x;    // < 131072
        int w  = idx >> 14;
        int s  = (idx >> 13) & 1;
        int hf = (idx >> 12) & 1;
        int kk = (idx >> 7) & 31;
        int n  = idx & 127;
        const float* src = (w == 0) ? qw : (w == 1) ? kw : (w == 2) ? vw : pw;
        int c = hf * 64 + 2 * kk;
        float v0 = src[s * 16384 + c * 128 + n];
        float v1 = src[s * 16384 + (c + 1) * 128 + n];
        d_wh[idx] = pkh2(v0, v1);
    } else {
        __shared__ float acc[NHEADS];
        int p = blockIdx.x - 512;                    // 0..224
        int j = threadIdx.x;                         // 0..255; hidden dim is 128
        if (j < NHEADS) acc[j] = 0.f;
        __syncthreads();
        float t0 = rpb[p * 2 + 0];
        float t1 = rpb[p * 2 + 1];
        float hid = 0.f;
        if (j < 128) hid = fmaxf(t0 * w1[j] + t1 * w1[128 + j] + b1[j], 0.f);
#pragma unroll
        for (int h = 0; h < NHEADS; ++h) {
            float pv = (j < 128) ? hid * w2[j * 8 + h] : 0.f;
#pragma unroll
            for (int o = 16; o; o >>= 1) pv += __shfl_xor_sync(0xffffffffu, pv, o);
            if ((j & 31) == 0) atomicAdd(&acc[h], pv);
        }
        __syncthreads();
        if (j < NHEADS) d_tbl2[p * 8 + j] = acc[j];
    }
}

// ---------------- prologue 2: combined bias+mask table ----------------
__global__ void bias_combine_kernel(const int* __restrict__ rpi,
                                    const float* __restrict__ mask) {
    int idx = blockIdx.x * blockDim.x + threadIdx.x;
    if (idx >= NWIN * NHEADS * NTOK * NTOK) return;
    int ij = idx & 4095;
    int h  = (idx >> 12) & 7;
    int w  = idx >> 15;
    float bv = d_tbl2[rpi[ij] * 8 + h];
    d_Tcomb[idx] = 16.f / (1.f + expf(-bv)) + mask[w * 4096 + ij];
}

// ---------------- fp16 mma m16n8k16 ----------------
__device__ __forceinline__ void mma_f16(float& d0, float& d1, float& d2, float& d3,
                                        uint32_t a0, uint32_t a1, uint32_t a2, uint32_t a3,
                                        uint32_t b0, uint32_t b1) {
    asm volatile(
        "mma.sync.aligned.m16n8k16.row.col.f32.f16.f16.f32 "
        "{%0,%1,%2,%3},{%4,%5,%6,%7},{%8,%9},{%0,%1,%2,%3};"
        : "+f"(d0), "+f"(d1), "+f"(d2), "+f"(d3)
        : "r"(a0), "r"(a1), "r"(a2), "r"(a3), "r"(b0), "r"(b1));
}

// weight source: w 0..3 = q,k,v,p; half hf -> [32 kk][128 n] uint32 block
#define WSRC(w, hf) (d_wh + (((w) * 2 + s) * 2 + (hf)) * 4096)

// stage one [32 kk][128 n] uint32 weight half via 4 cp.async per thread
#define ISSUE(SRC, DSTU) do {                                                \
    const uint32_t* _s0 = (SRC) + ldrow * 128 + ldcol;                       \
    uint32_t _d0 = (DSTU) + (uint32_t)((ldrow * S2W + ldcol) * 4);           \
    _Pragma("unroll")                                                        \
    for (int k_ = 0; k_ < 4; ++k_)                                           \
        asm volatile("cp.async.cg.shared.global [%0], [%1], 16;\n"           \
            :: "r"(_d0 + (uint32_t)(k_ * 8 * S2W * 4)),                      \
               "l"(_s0 + k_ * 8 * 128) : "memory");                          \
    asm volatile("cp.async.commit_group;\n" ::: "memory");                   \
} while (0)

#define WAITSYNC() do {                                                      \
    asm volatile("cp.async.wait_group 0;\n" ::: "memory");                   \
    __syncthreads();                                                         \
} while (0)

// 32x32 warp-tile fp16 mma over one staged weight half, A from af (current half)
#define MMA_LOOP(BUFU, ACC) do {                                             \
    const uint32_t* _bu = (BUFU);                                            \
    _Pragma("unroll")                                                        \
    for (int kt = 0; kt < 4; ++kt) {                                         \
        const uint32_t* bp = _bu + (kt * 8 + ql) * S2W + n0 + qr;            \
        _Pragma("unroll")                                                    \
        for (int nt = 0; nt < 4; ++nt) {                                     \
            uint32_t b0_ = bp[nt * 8], b1_ = bp[4 * S2W + nt * 8];           \
            mma_f16(ACC[0][nt][0], ACC[0][nt][1], ACC[0][nt][2], ACC[0][nt][3], \
                    af[0][kt][0], af[0][kt][1], af[0][kt][2], af[0][kt][3],  \
                    b0_, b1_);                                               \
            mma_f16(ACC[1][nt][0], ACC[1][nt][1], ACC[1][nt][2], ACC[1][nt][3], \
                    af[1][kt][0], af[1][kt][1], af[1][kt][2], af[1][kt][3],  \
                    b0_, b1_);                                               \
        }                                                                    \
    }                                                                        \
} while (0)

// load A fragments for half HF into af (2 row tiles x 4 k16 tiles, 32 regs)
#define LOAD_AF(HF) do {                                                     \
    _Pragma("unroll")                                                        \
    for (int mt = 0; mt < 2; ++mt)                                           \
    _Pragma("unroll")                                                        \
    for (int kt = 0; kt < 4; ++kt) {                                         \
        const uint32_t* ap = qs2 + (r0 + mt * 16 + qr) * S2Q + (HF) * 32 + kt * 8 + ql; \
        af[mt][kt][0] = ap[0];                                               \
        af[mt][kt][1] = ap[8 * S2Q];                                         \
        af[mt][kt][2] = ap[4];                                               \
        af[mt][kt][3] = ap[8 * S2Q + 4];                                     \
    }                                                                        \
} while (0)

#define ZERO_ACC(A) do {                                                     \
    _Pragma("unroll")                                                        \
    for (int mt = 0; mt < 2; ++mt)                                           \
    _Pragma("unroll")                                                        \
    for (int nt = 0; nt < 4; ++nt)                                           \
        { A[mt][nt][0] = 0.f; A[mt][nt][1] = 0.f; A[mt][nt][2] = 0.f; A[mt][nt][3] = 0.f; } \
} while (0)

// ---------------- main fused kernel: one CTA per (window, branch), 3 CTAs/SM ----------------
__global__ void __launch_bounds__(THREADS, 3)
swin_branch_kernel(const float* __restrict__ x,
                   const float* __restrict__ qb, const float* __restrict__ kb,
                   const float* __restrict__ vb, const float* __restrict__ pb,
                   const float* __restrict__ ls, float* __restrict__ out)
{
    extern __shared__ uint32_t smU[];
    uint32_t* qs2   = smU + OFF_Q;    // x / q / O as fp16 pairs (64 x 68)
    uint32_t* kbufU = smU + OFF_K;    // K d-pair transposed [d/2=64][key 64] (stride 72)
    uint32_t* vbufU = smU + OFF_V;    // V token-pair [tok/2=32][d 128] / stage overlay
    uint32_t* wst   = smU + OFF_W;    // dedicated weight stage

    const int bid  = blockIdx.x;
    const int win  = bid >> 1;
    const int s    = bid & 1;               // branch (heads s*4..s*4+3)
    const int tid  = threadIdx.x;
    const int warp = tid >> 5;
    const int lane = tid & 31;
    const int r0   = (warp & 1) * 32;       // 32x32 warp tiles: 2 row x 4 col grid
    const int n0   = (warp >> 1) * 32;      // col tile == one head
    const int qr   = lane >> 2;
    const int ql   = lane & 3;
    const int ldrow = tid >> 5;             // staging row base 0..7
    const int ldcol = (tid & 31) * 4;       // staging col (uint32) 0..124

    const uint32_t wst_u  = (uint32_t)__cvta_generic_to_shared(wst);
    const uint32_t vstg_u = (uint32_t)__cvta_generic_to_shared(vbufU);

    uint32_t af[2][4][4];                   // A frags for the CURRENT half only

    // prefetch K weights (both halves) into wst + vbuf overlay
    ISSUE(WSRC(1, 0), wst_u);
    ISSUE(WSRC(1, 1), vstg_u);

    const float qscale = fminf(expf(ls[s * 4 + (warp >> 1)]), 100.f);

    // load x branch slice [64][128] -> fp16 pairs in qs
    const float4* xg4 = (const float4*)(x + (size_t)win * (NTOK * CDIM));
    for (int t = tid; t < 64 * 32; t += THREADS) {
        int i = t >> 5, j = t & 31;
        float4 v = xg4[i * 64 + s * 32 + j];
        uint2 st; st.x = pkh2(v.x, v.y); st.y = pkh2(v.z, v.w);
        *(uint2*)&qs2[i * S2Q + j * 2] = st;
    }
    WAITSYNC();                              // B1: x visible + K weights landed

    // =========== Phase 1: K, V, Q residual linears ===========
    {
        // --- K GEMM ---
        float acc[2][4][4];
        ZERO_ACC(acc);
        LOAD_AF(0); MMA_LOOP(wst, acc);
        LOAD_AF(1); MMA_LOOP(vbufU, acc);
        __syncthreads();                     // B2: stage reads done
        ISSUE(WSRC(2, 0), wst_u);            // V weights
        ISSUE(WSRC(2, 1), vstg_u);

        // k epilogue: in-place acc = x+acc+kb, quad-reduce row norms (fp32),
        // store NORMALIZED fp16 pairs -> kbuf d-pair transposed [c/2][key]
#pragma unroll
        for (int mt = 0; mt < 2; ++mt) {
            const int rr = r0 + mt * 16 + qr;
            float ssq0 = 0.f, ssq1 = 0.f;
#pragma unroll
            for (int nt = 0; nt < 4; ++nt) {
                const int c = n0 + nt * 8 + 2 * ql;
                float2 x0 = uph2(qs2[rr * S2Q + (c >> 1)]);
                float2 x1 = uph2(qs2[(rr + 8) * S2Q + (c >> 1)]);
                float2 kb2 = *(const float2*)&kb[s * 128 + c];
                acc[mt][nt][0] = x0.x + acc[mt][nt][0] + kb2.x;
                acc[mt][nt][1] = x0.y + acc[mt][nt][1] + kb2.y;
                acc[mt][nt][2] = x1.x + acc[mt][nt][2] + kb2.x;
                acc[mt][nt][3] = x1.y + acc[mt][nt][3] + kb2.y;
                ssq0 = fmaf(acc[mt][nt][0], acc[mt][nt][0], fmaf(acc[mt][nt][1], acc[mt][nt][1], ssq0));
                ssq1 = fmaf(acc[mt][nt][2], acc[mt][nt][2], fmaf(acc[mt][nt][3], acc[mt][nt][3], ssq1));
            }
            ssq0 += __shfl_xor_sync(0xffffffffu, ssq0, 1);
            ssq0 += __shfl_xor_sync(0xffffffffu, ssq0, 2);
            ssq1 += __shfl_xor_sync(0xffffffffu, ssq1, 1);
            ssq1 += __shfl_xor_sync(0xffffffffu, ssq1, 2);
            float inv0 = 1.f / fmaxf(sqrtf(ssq0), 1e-12f);
            float inv1 = 1.f / fmaxf(sqrtf(ssq1), 1e-12f);
#pragma unroll
            for (int nt = 0; nt < 4; ++nt) {
                const int c = n0 + nt * 8 + 2 * ql;
                kbufU[(c >> 1) * S2K + rr] =
                    pkh2(acc[mt][nt][0] * inv0, acc[mt][nt][1] * inv0);
                kbufU[(c >> 1) * S2K + rr + 8] =
                    pkh2(acc[mt][nt][2] * inv1, acc[mt][nt][3] * inv1);
            }
        }
    }
    WAITSYNC();                              // B3: V weights landed (+k published)
    {
        // --- V GEMM ---
        float acc[2][4][4];
        ZERO_ACC(acc);
        LOAD_AF(0); MMA_LOOP(wst, acc);
        LOAD_AF(1); MMA_LOOP(vbufU, acc);
        __syncthreads();                     // B4: vbuf stage reads done
        ISSUE(WSRC(0, 0), wst_u);            // Q weights h0 (wst free)

        // v epilogue: token-pair pack via lane-xor-4 exchange -> vbuf
#pragma unroll
        for (int mt = 0; mt < 2; ++mt) {
            const int rr = r0 + mt * 16 + qr;
            const int m0 = rr >> 1;
            const uint32_t psel = (qr & 1) ? 0x3276u : 0x5410u;
            const int cofs = (qr & 1);
#pragma unroll
            for (int nt = 0; nt < 4; ++nt) {
                const int c = n0 + nt * 8 + 2 * ql;
                float2 x0 = uph2(qs2[rr * S2Q + (c >> 1)]);
                float2 x1 = uph2(qs2[(rr + 8) * S2Q + (c >> 1)]);
                float2 vb2 = *(const float2*)&vb[s * 128 + c];
                uint32_t mine0 = pkh2(x0.x + acc[mt][nt][0] + vb2.x, x0.y + acc[mt][nt][1] + vb2.y);
                uint32_t mine1 = pkh2(x1.x + acc[mt][nt][2] + vb2.x, x1.y + acc[mt][nt][3] + vb2.y);
                uint32_t oth0 = __shfl_xor_sync(0xffffffffu, mine0, 4);
                uint32_t oth1 = __shfl_xor_sync(0xffffffffu, mine1, 4);
                vbufU[m0 * S2V + c + cofs]       = __byte_perm(mine0, oth0, psel);
                vbufU[(m0 + 4) * S2V + c + cofs] = __byte_perm(mine1, oth1, psel);
            }
        }
    }
    WAITSYNC();                              // B5: Q-h0 landed (+v published)
    {
        // --- Q GEMM (single stage buffer: h0 then h1) ---
        float acc[2][4][4];
        ZERO_ACC(acc);
        LOAD_AF(0); MMA_LOOP(wst, acc);
        __syncthreads();                     // B6: wst reads done
        ISSUE(WSRC(0, 1), wst_u);            // Q weights h1
        WAITSYNC();                          // B7
        LOAD_AF(1); MMA_LOOP(wst, acc);

        // q epilogue: own-position RMW on qs, NORMALIZED with scale
#pragma unroll
        for (int mt = 0; mt < 2; ++mt) {
            const int rr = r0 + mt * 16 + qr;
            float ssq0 = 0.f, ssq1 = 0.f;
#pragma unroll
            for (int nt = 0; nt < 4; ++nt) {
                const int c = n0 + nt * 8 + 2 * ql;
                float2 x0 = uph2(qs2[rr * S2Q + (c >> 1)]);
                float2 x1 = uph2(qs2[(rr + 8) * S2Q + (c >> 1)]);
                float2 qb2 = *(const float2*)&qb[s * 128 + c];
                acc[mt][nt][0] = x0.x + acc[mt][nt][0] + qb2.x;
                acc[mt][nt][1] = x0.y + acc[mt][nt][1] + qb2.y;
                acc[mt][nt][2] = x1.x + acc[mt][nt][2] + qb2.x;
                acc[mt][nt][3] = x1.y + acc[mt][nt][3] + qb2.y;
                ssq0 = fmaf(acc[mt][nt][0], acc[mt][nt][0], fmaf(acc[mt][nt][1], acc[mt][nt][1], ssq0));
                ssq1 = fmaf(acc[mt][nt][2], acc[mt][nt][2], fmaf(acc[mt][nt][3], acc[mt][nt][3], ssq1));
            }
            ssq0 += __shfl_xor_sync(0xffffffffu, ssq0, 1);
            ssq0 += __shfl_xor_sync(0xffffffffu, ssq0, 2);
            ssq1 += __shfl_xor_sync(0xffffffffu, ssq1, 1);
            ssq1 += __shfl_xor_sync(0xffffffffu, ssq1, 2);
            float inv0 = qscale / fmaxf(sqrtf(ssq0), 1e-12f);
            float inv1 = qscale / fmaxf(sqrtf(ssq1), 1e-12f);
#pragma unroll
            for (int nt = 0; nt < 4; ++nt) {
                const int c = n0 + nt * 8 + 2 * ql;
                qs2[rr * S2Q + (c >> 1)] =
                    pkh2(acc[mt][nt][0] * inv0, acc[mt][nt][1] * inv0);
                qs2[(rr + 8) * S2Q + (c >> 1)] =
                    pkh2(acc[mt][nt][2] * inv1, acc[mt][nt][3] * inv1);
            }
        }
    }
    __syncthreads();                         // B8: q/k/v all published, wst reads done
    ISSUE(WSRC(3, 0), wst_u);                // P weights h0 (consumed in phase 4)

    // =========== Phase 3: attention (fp16 mma), two warps per head ===========
    {
        const int h = warp >> 1;
        const int mtb = (warp & 1) * 2;
        const float* Tw = d_Tcomb +
            (size_t)((((win & (NWIN - 1)) * NHEADS + s * 4 + h)) << 12);

#pragma unroll 1
        for (int mm = 0; mm < 2; ++mm) {
            const int i0r = (mtb + mm) * 16 + qr;

            uint32_t qa[2][4];
#pragma unroll
            for (int kt = 0; kt < 2; ++kt) {
                const uint32_t* ap = qs2 + i0r * S2Q + h * 16 + kt * 8 + ql;
                qa[kt][0] = ap[0];
                qa[kt][1] = ap[8 * S2Q];
                qa[kt][2] = ap[4];
                qa[kt][3] = ap[8 * S2Q + 4];
            }

            float S[8][4];
#pragma unroll
            for (int nt = 0; nt < 8; ++nt) { S[nt][0] = S[nt][1] = S[nt][2] = S[nt][3] = 0.f; }
#pragma unroll
            for (int kt = 0; kt < 2; ++kt) {
                const uint32_t* bp = kbufU + (h * 16 + kt * 8 + ql) * S2K + qr;
#pragma unroll
                for (int nt = 0; nt < 8; ++nt) {
                    mma_f16(S[nt][0], S[nt][1], S[nt][2], S[nt][3],
                            qa[kt][0], qa[kt][1], qa[kt][2], qa[kt][3],
                            bp[nt * 8], bp[4 * S2K + nt * 8]);
                }
            }

            float rmax0 = -1e30f, rmax1 = -1e30f;
#pragma unroll
            for (int nt = 0; nt < 8; ++nt) {
                float2 t0 = *(const float2*)&Tw[i0r * 64 + nt * 8 + 2 * ql];
                float2 t1 = *(const float2*)&Tw[(i0r + 8) * 64 + nt * 8 + 2 * ql];
                S[nt][0] += t0.x; S[nt][1] += t0.y;
                S[nt][2] += t1.x; S[nt][3] += t1.y;
                rmax0 = fmaxf(rmax0, fmaxf(S[nt][0], S[nt][1]));
                rmax1 = fmaxf(rmax1, fmaxf(S[nt][2], S[nt][3]));
            }
            rmax0 = fmaxf(rmax0, __shfl_xor_sync(0xffffffffu, rmax0, 1));
            rmax0 = fmaxf(rmax0, __shfl_xor_sync(0xffffffffu, rmax0, 2));
            rmax1 = fmaxf(rmax1, __shfl_xor_sync(0xffffffffu, rmax1, 1));
            rmax1 = fmaxf(rmax1, __shfl_xor_sync(0xffffffffu, rmax1, 2));

            float sum0 = 0.f, sum1 = 0.f;
#pragma unroll
            for (int nt = 0; nt < 8; ++nt) {
                S[nt][0] = __expf(S[nt][0] - rmax0); sum0 += S[nt][0];
                S[nt][1] = __expf(S[nt][1] - rmax0); sum0 += S[nt][1];
                S[nt][2] = __expf(S[nt][2] - rmax1); sum1 += S[nt][2];
                S[nt][3] = __expf(S[nt][3] - rmax1); sum1 += S[nt][3];
            }
            sum0 += __shfl_xor_sync(0xffffffffu, sum0, 1);
            sum0 += __shfl_xor_sync(0xffffffffu, sum0, 2);
            sum1 += __shfl_xor_sync(0xffffffffu, sum1, 1);
            sum1 += __shfl_xor_sync(0xffffffffu, sum1, 2);
            float inv0 = 1.f / sum0, inv1 = 1.f / sum1;

            // P -> A-fragments: fp16 C/A layouts coincide, no shuffles
            uint32_t pa[4][4];
#pragma unroll
            for (int kt = 0; kt < 4; ++kt) {
                pa[kt][0] = pkh2(S[2 * kt][0] * inv0, S[2 * kt][1] * inv0);
                pa[kt][1] = pkh2(S[2 * kt][2] * inv1, S[2 * kt][3] * inv1);
                pa[kt][2] = pkh2(S[2 * kt + 1][0] * inv0, S[2 * kt + 1][1] * inv0);
                pa[kt][3] = pkh2(S[2 * kt + 1][2] * inv1, S[2 * kt + 1][3] * inv1);
            }

            float O[4][4];
#pragma unroll
            for (int nd = 0; nd < 4; ++nd) { O[nd][0] = O[nd][1] = O[nd][2] = O[nd][3] = 0.f; }
#pragma unroll
            for (int kt = 0; kt < 4; ++kt) {
                const uint32_t* vp = vbufU + (kt * 8 + ql) * S2V + h * 32 + qr;
#pragma unroll
                for (int nd = 0; nd < 4; ++nd) {
                    mma_f16(O[nd][0], O[nd][1], O[nd][2], O[nd][3],
                            pa[kt][0], pa[kt][1], pa[kt][2], pa[kt][3],
                            vp[nd * 8], vp[4 * S2V + nd * 8]);
                }
            }

            // O (already normalized) -> fp16 pairs into qs
#pragma unroll
            for (int nd = 0; nd < 4; ++nd) {
                qs2[i0r * S2Q + h * 16 + nd * 4 + ql] = pkh2(O[nd][0], O[nd][1]);
                qs2[(i0r + 8) * S2Q + h * 16 + nd * 4 + ql] = pkh2(O[nd][2], O[nd][3]);
            }
        }
    }
    WAITSYNC();                              // B9: phase-3 writes visible + P-h0 landed

    // =========== Phase 4: output projection (single stage buffer) ===========
    float* og = out + (size_t)win * (NTOK * CDIM);
    {
        float acc[2][4][4];
        ZERO_ACC(acc);
        LOAD_AF(0); MMA_LOOP(wst, acc);
        __syncthreads();                     // B10: wst reads done
        ISSUE(WSRC(3, 1), wst_u);            // P weights h1
        WAITSYNC();                          // B11
        LOAD_AF(1); MMA_LOOP(wst, acc);

#pragma unroll
        for (int mt = 0; mt < 2; ++mt) {
            const int rr = r0 + mt * 16 + qr;
#pragma unroll
            for (int nt = 0; nt < 4; ++nt) {
                const int c = n0 + nt * 8 + 2 * ql;
                float2 pb2 = *(const float2*)&pb[s * 128 + c];
                *(float2*)&og[rr * CDIM + s * 128 + c] =
                    make_float2(acc[mt][nt][0] + pb2.x, acc[mt][nt][1] + pb2.y);
                *(float2*)&og[(rr + 8) * CDIM + s * 128 + c] =
                    make_float2(acc[mt][nt][2] + pb2.x, acc[mt][nt][3] + pb2.y);
            }
        }
    }
}

extern "C" void kernel_launch(void* const* d_in, const int* in_sizes, int n_in,
                              void* d_out, int out_size) {
    const float* x    = (const float*)d_in[0];
    const float* mask = (const float*)d_in[1];
    const float* qw   = (const float*)d_in[2];
    const float* qb   = (const float*)d_in[3];
    const float* kw   = (const float*)d_in[4];
    const float* kb   = (const float*)d_in[5];
    const float* vw   = (const float*)d_in[6];
    const float* vb   = (const float*)d_in[7];
    const float* pw   = (const float*)d_in[8];
    const float* pb   = (const float*)d_in[9];
    const float* w1   = (const float*)d_in[10];
    const float* b1   = (const float*)d_in[11];
    const float* w2   = (const float*)d_in[12];
    const float* ls   = (const float*)d_in[13];
    const float* rpb  = (const float*)d_in[14];
    const int*   rpi  = (const int*)d_in[15];
    float* out = (float*)d_out;

    static bool inited = false;
    if (!inited) {
        cudaFuncSetAttribute(swin_branch_kernel,
                             cudaFuncAttributeMaxDynamicSharedMemorySize, SMEM_BYTES);
        inited = true;
    }

    prologue_kernel<<<737, 256>>>(qw, kw, vw, pw, rpb, w1, b1, w2);
    bias_combine_kernel<<<(NWIN * NHEADS * NTOK * NTOK + 255) / 256, 256>>>(rpi, mask);
    swin_branch_kernel<<<NBATCH * 2, THREADS, SMEM_BYTES>>>(x, qb, kb, vb, pb, ls, out);
}